// round 2
// baseline (speedup 1.0000x reference)
#include <cuda_runtime.h>
#include <cuda_bf16.h>
#include <math.h>

// Problem shape (fixed): output [B=2, C=8, H=128, W=128, D=128] fp32.
// Slice (one (b,c)) = 128^3 = 2,097,152 elems = 524,288 float4.
// Grid: 16 slices * 64 blocks = 1024 blocks, 256 threads.
// Each block: 524288/64 = 8192 float4 = 32 per thread.

#define NSLICE       16
#define BLK_PER_SL   64
#define THREADS      256
#define F4_PER_BLK   8192  // float4 per block
#define SLICE_F4     524288

// per-block partials: [slice][blk] -> float4 {s, sum_t*h, sum_t*w, sum_t*d}
__device__ float4 g_partial[NSLICE * BLK_PER_SL];

__global__ __launch_bounds__(THREADS) void reduce_kernel(const float* __restrict__ in) {
    const int bc  = blockIdx.x >> 6;        // slice 0..15
    const int blk = blockIdx.x & 63;        // block within slice
    const int tid = threadIdx.x;

    const float4* __restrict__ p =
        reinterpret_cast<const float4*>(in) + (size_t)bc * SLICE_F4 + (size_t)blk * F4_PER_BLK;

    float s = 0.f, sy = 0.f, sx = 0.f, sz = 0.f;

#pragma unroll 8
    for (int i = tid; i < F4_PER_BLK; i += THREADS) {
        float4 v = p[i];
        // element index within the slice for lane .x of this float4
        // global elem within slice = (blk*F4_PER_BLK + i) * 4
        int e = (blk * F4_PER_BLK + i) << 2;
        float t0 = v.x > 0.5f ? v.x : 0.f;
        float t1 = v.y > 0.5f ? v.y : 0.f;
        float t2 = v.z > 0.5f ? v.z : 0.f;
        float t3 = v.w > 0.5f ? v.w : 0.f;
        float tsum = (t0 + t1) + (t2 + t3);

        float fh = (float)(e >> 14);          // h = e / (128*128)
        float fw = (float)((e >> 7) & 127);   // w
        float fd = (float)(e & 127);          // d of lane .x (lanes: d, d+1, d+2, d+3)

        s += tsum;
        sy = fmaf(tsum, fh, sy);
        sx = fmaf(tsum, fw, sx);
        // sum t*d over the 4 lanes = tsum*fd + (t1 + 2*t2 + 3*t3)
        sz = fmaf(tsum, fd, sz) + (t1 + 2.f * t2 + 3.f * t3);
    }

    // warp reduction
    const unsigned FULL = 0xFFFFFFFFu;
#pragma unroll
    for (int off = 16; off > 0; off >>= 1) {
        s  += __shfl_down_sync(FULL, s,  off);
        sy += __shfl_down_sync(FULL, sy, off);
        sx += __shfl_down_sync(FULL, sx, off);
        sz += __shfl_down_sync(FULL, sz, off);
    }

    __shared__ float4 warp_acc[THREADS / 32];
    int lane = tid & 31;
    int wid  = tid >> 5;
    if (lane == 0) warp_acc[wid] = make_float4(s, sy, sx, sz);
    __syncthreads();

    if (wid == 0) {
        float4 a = (lane < THREADS / 32) ? warp_acc[lane] : make_float4(0.f, 0.f, 0.f, 0.f);
#pragma unroll
        for (int off = 4; off > 0; off >>= 1) {
            a.x += __shfl_down_sync(FULL, a.x, off);
            a.y += __shfl_down_sync(FULL, a.y, off);
            a.z += __shfl_down_sync(FULL, a.z, off);
            a.w += __shfl_down_sync(FULL, a.w, off);
        }
        if (lane == 0) g_partial[bc * BLK_PER_SL + blk] = a;
    }
}

// Relations table: (i, j, gy, gx, gz)
__device__ __constant__ int   c_ri[8] = {0, 1, 2, 3, 4, 5, 6, 0};
__device__ __constant__ int   c_rj[8] = {1, 2, 3, 4, 5, 6, 7, 7};
__device__ __constant__ float c_gy[8] = { 0.1f, 0.0f, -0.1f, 0.0f,  0.05f, 0.0f,  0.1f, -0.05f};
__device__ __constant__ float c_gx[8] = { 0.0f, 0.1f,  0.05f, 0.0f, -0.05f, 0.1f, 0.0f,  0.05f};
__device__ __constant__ float c_gz[8] = { 0.05f, 0.0f, 0.0f,  0.1f,  0.0f, -0.1f, 0.0f,  0.05f};

__global__ __launch_bounds__(1024) void finalize_kernel(float* __restrict__ out) {
    __shared__ float4 sh[NSLICE * BLK_PER_SL];          // 16 KB
    __shared__ float cent[NSLICE][3];                   // cy, cx, cz per (b,c)

    int tid = threadIdx.x;
    sh[tid] = g_partial[tid];
    __syncthreads();

    if (tid < NSLICE) {
        float s = 0.f, sy = 0.f, sx = 0.f, sz = 0.f;
#pragma unroll
        for (int k = 0; k < BLK_PER_SL; k++) {
            float4 a = sh[tid * BLK_PER_SL + k];
            s += a.x; sy += a.y; sx += a.z; sz += a.w;
        }
        const float inv128 = 1.0f / 128.0f;
        float inv_s = 1.0f / s;                 // may be inf if s==0; guarded below
        cent[tid][0] = sy * inv_s * inv128;
        cent[tid][1] = sx * inv_s * inv128;
        cent[tid][2] = sz * inv_s * inv128;
    }
    __syncthreads();

    if (tid == 0) {
        // channel c of batch b is slice index b*8 + c
        float loss = 0.f;
#pragma unroll
        for (int r = 0; r < 8; r++) {
            int i = c_ri[r], j = c_rj[r];
            float acc_y = 0.f, acc_x = 0.f, acc_z = 0.f;
#pragma unroll
            for (int b = 0; b < 2; b++) {
                float dy = cent[b * 8 + i][0] - cent[b * 8 + j][0] - c_gy[r];
                float dx = cent[b * 8 + i][1] - cent[b * 8 + j][1] - c_gx[r];
                float dz = cent[b * 8 + i][2] - cent[b * 8 + j][2] - c_gz[r];
                if (!isfinite(dy)) dy = 0.f;
                if (!isfinite(dx)) dx = 0.f;
                if (!isfinite(dz)) dz = 0.f;
                acc_y += dy * dy;
                acc_x += dx * dx;
                acc_z += dz * dz;
            }
            loss += 0.5f * (acc_y + acc_x + acc_z);   // mean over batch (B=2)
        }
        out[0] = loss;
    }
}

extern "C" void kernel_launch(void* const* d_in, const int* in_sizes, int n_in,
                              void* d_out, int out_size) {
    const float* in = (const float*)d_in[0];
    float* out = (float*)d_out;
    (void)in_sizes; (void)n_in; (void)out_size;

    reduce_kernel<<<NSLICE * BLK_PER_SL, THREADS>>>(in);
    finalize_kernel<<<1, 1024>>>(out);
}